// round 4
// baseline (speedup 1.0000x reference)
#include <cuda_runtime.h>
#include <cuda_bf16.h>

#define N_CLASSES 26
#define IMG 68
#define BATCH 8192
#define NEXP 64
#define FC1N 500
#define FLATN 1960

// scratch (device globals; no allocation allowed)
__device__ __align__(16) float g_p1[N_CLASSES * 5 * 32 * 32];
__device__ __align__(16) float g_hcls[N_CLASSES * FLATN];
__device__ __align__(16) float g_u[N_CLASSES * FC1N];
__device__ __align__(16) float2 g_wx[FC1N];
__device__ __align__(16) float g_w2t[FC1N * NEXP];   // [k][e]

// ---------------------------------------------------------------------------
// Kernel A1: conv1 (5x5, 1->5) + relu + maxpool2 per (class, channel).
// Side work: transpose fc2_w -> g_w2t, extract fc1_w x-columns -> g_wx.
// grid = 130, block = 512.
// ---------------------------------------------------------------------------
__global__ void conv1_kernel(const float* __restrict__ images,
                             const float* __restrict__ w1,
                             const float* __restrict__ b1,
                             const float* __restrict__ fc1_w,
                             const float* __restrict__ fc2_w) {
    __shared__ float s_img[IMG * IMG];
    __shared__ float s_w[25];
    int c = blockIdx.x / 5, ch = blockIdx.x % 5;
    int tid = threadIdx.x;

    int gt = blockIdx.x * 512 + tid;
    if (gt < NEXP * FC1N) {
        int e = gt / FC1N, k = gt - e * FC1N;
        g_w2t[k * NEXP + e] = fc2_w[gt];
    }
    if (gt < FC1N) {
        float2 v;
        v.x = fc1_w[gt * 1962 + 1960];
        v.y = fc1_w[gt * 1962 + 1961];
        g_wx[gt] = v;
    }

    const float* img = images + c * IMG * IMG;
    for (int i = tid; i < IMG * IMG; i += 512) s_img[i] = img[i];
    if (tid < 25) s_w[tid] = w1[ch * 25 + tid];
    __syncthreads();
    float bb = b1[ch];
    float wr[25];
#pragma unroll
    for (int i = 0; i < 25; i++) wr[i] = s_w[i];
    float* outp = g_p1 + (c * 5 + ch) * 1024;
    for (int i = tid; i < 1024; i += 512) {
        int oy = i >> 5, ox = i & 31;
        int y0 = 2 * oy, x0 = 2 * ox;
        float p[6][6];
#pragma unroll
        for (int r = 0; r < 6; r++)
#pragma unroll
            for (int cc = 0; cc < 6; cc++) p[r][cc] = s_img[(y0 + r) * IMG + x0 + cc];
        float a00 = bb, a01 = bb, a10 = bb, a11 = bb;
#pragma unroll
        for (int ky = 0; ky < 5; ky++)
#pragma unroll
            for (int kx = 0; kx < 5; kx++) {
                float w = wr[ky * 5 + kx];
                a00 = fmaf(p[ky][kx], w, a00);
                a01 = fmaf(p[ky][kx + 1], w, a01);
                a10 = fmaf(p[ky + 1][kx], w, a10);
                a11 = fmaf(p[ky + 1][kx + 1], w, a11);
            }
        outp[i] = fmaxf(fmaxf(fmaxf(a00, a01), fmaxf(a10, a11)), 0.f);
    }
}

// ---------------------------------------------------------------------------
// Kernel A2: conv2 (5x5, 5->10) + relu + maxpool2. grid = 260, block = 256.
// ---------------------------------------------------------------------------
__global__ void conv2_kernel(const float* __restrict__ w2,
                             const float* __restrict__ b2) {
    __shared__ float s_p1[5 * 1024];
    __shared__ float s_w[125];
    int c = blockIdx.x / 10, co = blockIdx.x % 10;
    int tid = threadIdx.x;
    for (int i = tid; i < 5120; i += 256) s_p1[i] = g_p1[c * 5120 + i];
    if (tid < 125) s_w[tid] = w2[co * 125 + tid];
    __syncthreads();
    float bb = b2[co];
    for (int i = tid; i < 196; i += 256) {
        int oy = i / 14, ox = i % 14;
        int y0 = 2 * oy, x0 = 2 * ox;
        float a00 = bb, a01 = bb, a10 = bb, a11 = bb;
#pragma unroll
        for (int ci = 0; ci < 5; ci++) {
            const float* base = s_p1 + ci * 1024 + y0 * 32 + x0;
            float p[6][6];
#pragma unroll
            for (int r = 0; r < 6; r++)
#pragma unroll
                for (int cc = 0; cc < 6; cc++) p[r][cc] = base[r * 32 + cc];
            const float* wb = s_w + ci * 25;
#pragma unroll
            for (int ky = 0; ky < 5; ky++)
#pragma unroll
                for (int kx = 0; kx < 5; kx++) {
                    float w = wb[ky * 5 + kx];
                    a00 = fmaf(p[ky][kx], w, a00);
                    a01 = fmaf(p[ky][kx + 1], w, a01);
                    a10 = fmaf(p[ky + 1][kx], w, a10);
                    a11 = fmaf(p[ky + 1][kx + 1], w, a11);
                }
        }
        g_hcls[c * FLATN + co * 196 + i] =
            fmaxf(fmaxf(fmaxf(a00, a01), fmaxf(a10, a11)), 0.f);
    }
}

// ---------------------------------------------------------------------------
// Kernel B: fc1, single kernel (unchanged from round 3 — not the bottleneck).
// grid = 128 (32 out-tiles x 4 class-tiles), block = 256.
// ---------------------------------------------------------------------------
#define WROWP 1964
#define FC1SMEM ((16 * WROWP + 8 * WROWP + 1024) * 4)
__global__ void __launch_bounds__(256, 1) fc1_kernel(const float* __restrict__ fc1_w,
                                                     const float* __restrict__ fc1_b) {
    extern __shared__ float sm[];
    float* smW = sm;                    // [16][1964]
    float* smH = smW + 16 * WROWP;      // [8][1964]
    float* pbuf = smH + 8 * WROWP;      // [1024]
    int tid = threadIdx.x;
    int ot = blockIdx.x & 31, ct = blockIdx.x >> 5;

    for (int idx = tid; idx < 16 * 980; idx += 256) {
        int r = idx / 980, k2 = idx - r * 980;
        int row = ot * 16 + r;
        float2 v = (row < FC1N)
                       ? ((const float2*)(fc1_w + (long)row * 1962))[k2]
                       : make_float2(0.f, 0.f);
        *(float2*)(smW + r * WROWP + 2 * k2) = v;
    }
    for (int idx = tid; idx < 8 * 490; idx += 256) {
        int r = idx / 490, q = idx - r * 490;
        int ci = ct * 8 + r;
        float4 v = (ci < N_CLASSES)
                       ? ((const float4*)(g_hcls + ci * FLATN))[q]
                       : make_float4(0.f, 0.f, 0.f, 0.f);
        *(float4*)(smH + r * WROWP + 4 * q) = v;
    }
    __syncthreads();

    int o = tid & 15, cg = (tid >> 4) & 1, kq8 = tid >> 5;
    const float4* wq = (const float4*)(smW + o * WROWP);
    const float4* h0 = (const float4*)(smH + (4 * cg + 0) * WROWP);
    const float4* h1 = (const float4*)(smH + (4 * cg + 1) * WROWP);
    const float4* h2 = (const float4*)(smH + (4 * cg + 2) * WROWP);
    const float4* h3 = (const float4*)(smH + (4 * cg + 3) * WROWP);
    float a0 = 0.f, a1 = 0.f, a2 = 0.f, a3 = 0.f;
    for (int q = kq8; q < 490; q += 8) {
        float4 w = wq[q];
        float4 v0 = h0[q], v1 = h1[q], v2 = h2[q], v3 = h3[q];
        a0 = fmaf(w.x, v0.x, a0); a0 = fmaf(w.y, v0.y, a0);
        a0 = fmaf(w.z, v0.z, a0); a0 = fmaf(w.w, v0.w, a0);
        a1 = fmaf(w.x, v1.x, a1); a1 = fmaf(w.y, v1.y, a1);
        a1 = fmaf(w.z, v1.z, a1); a1 = fmaf(w.w, v1.w, a1);
        a2 = fmaf(w.x, v2.x, a2); a2 = fmaf(w.y, v2.y, a2);
        a2 = fmaf(w.z, v2.z, a2); a2 = fmaf(w.w, v2.w, a2);
        a3 = fmaf(w.x, v3.x, a3); a3 = fmaf(w.y, v3.y, a3);
        a3 = fmaf(w.z, v3.z, a3); a3 = fmaf(w.w, v3.w, a3);
    }
    pbuf[o + 16 * (4 * cg + 0) + 128 * kq8] = a0;
    pbuf[o + 16 * (4 * cg + 1) + 128 * kq8] = a1;
    pbuf[o + 16 * (4 * cg + 2) + 128 * kq8] = a2;
    pbuf[o + 16 * (4 * cg + 3) + 128 * kq8] = a3;
    __syncthreads();
    if (tid < 128) {
        int oo = tid & 15, c = tid >> 4;
        float s = 0.f;
#pragma unroll
        for (int j = 0; j < 8; j++) s += pbuf[oo + 16 * c + 128 * j];
        int cls = ct * 8 + c;
        int out = ot * 16 + oo;
        if (cls < N_CLASSES && out < FC1N)
            g_u[cls * FC1N + out] = s + fc1_b[out];
    }
}

// ---------------------------------------------------------------------------
// Kernel C: fused MoE. grid = 128, block = 512.
// ws resident for FULL K (staged once, from pre-transposed g_w2t, conflict-
// free float4 copies). hs double-phased (250 k each). Explicit prefetch-2
// software pipeline; padded rows absorb prefetch overrun.
// ---------------------------------------------------------------------------
#define TS 64
#define KP 250
#define WR 68           // ws row stride
#define WSROWS 504      // 500 + padding for prefetch overrun
#define HR 66           // hs row stride
#define HSROWS 254
#define LR 68
#define SMEMC ((WSROWS * WR + HSROWS * HR + TS * LR + 256 + 64 * 5 + 64) * 4)

#define FMA8(hv, wv)                                                            \
    do {                                                                        \
        unsigned long long hd0, hd1, w01, w23;                                  \
        asm("mov.b64 %0, {%1,%1};" : "=l"(hd0) : "f"(hv.x));                    \
        asm("mov.b64 %0, {%1,%1};" : "=l"(hd1) : "f"(hv.y));                    \
        asm("mov.b64 %0, {%1,%2};" : "=l"(w01) : "f"(wv.x), "f"(wv.y));         \
        asm("mov.b64 %0, {%1,%2};" : "=l"(w23) : "f"(wv.z), "f"(wv.w));         \
        asm("fma.rn.f32x2 %0, %1, %2, %0;" : "+l"(a00) : "l"(w01), "l"(hd0));   \
        asm("fma.rn.f32x2 %0, %1, %2, %0;" : "+l"(a01) : "l"(w23), "l"(hd0));   \
        asm("fma.rn.f32x2 %0, %1, %2, %0;" : "+l"(a10) : "l"(w01), "l"(hd1));   \
        asm("fma.rn.f32x2 %0, %1, %2, %0;" : "+l"(a11) : "l"(w23), "l"(hd1));   \
    } while (0)

__global__ void __launch_bounds__(512, 1)
moe_kernel(const float* __restrict__ x, const int* __restrict__ cls_idx,
           const float* __restrict__ fc2_b,
           const float* __restrict__ A_B, const float* __restrict__ A_C,
           const float* __restrict__ x_tar, float* __restrict__ out) {
    extern __shared__ float sm[];
    float* ws = sm;                       // [504][68] k-major experts (full K)
    float* hs = ws + WSROWS * WR;         // [254][66] k-major samples (per phase)
    float* Ls = hs + HSROWS * HR;         // [64][68]
    float* Gs = Ls + TS * LR;             // [64][4]
    float* b2s = Gs + 256;
    float* sx0 = b2s + 64;
    float* sx1 = sx0 + 64;
    float* sd0 = sx1 + 64;
    float* sd1 = sd0 + 64;
    int* scls = (int*)(sd1 + 64);

    int tid = threadIdx.x, lane = tid & 31, warp = tid >> 5;  // 16 warps
    int base = blockIdx.x * TS;

    // stage ws: 8000 float4 copies of pre-transposed fc2_w, conflict-free
    {
        const float4* src = (const float4*)g_w2t;
        for (int idx = tid; idx < FC1N * 16; idx += 512) {
            int k = idx >> 4, e4 = idx & 15;
            *(float4*)(ws + k * WR + 4 * e4) = src[idx];
        }
    }
    if (tid < 256) Gs[tid] = A_B[tid] + A_C[tid];
    if (tid < 64) b2s[tid] = fc2_b[tid];
    if (tid < TS) {
        int s = base + tid;
        float x0v = x[2 * s], x1v = x[2 * s + 1];
        sx0[tid] = x0v; sx1[tid] = x1v;
        sd0[tid] = x_tar[0] - x0v;
        sd1[tid] = x_tar[1] - x1v;
        scls[tid] = cls_idx[s];
    }
    __syncthreads();  // scls/sx ready for fill

    int eg = lane & 1, sg = lane >> 1;
    int sblk = warp & 1, eblk = warp >> 1;
    int s0 = 32 * sblk + 2 * sg;
    int e0 = 8 * eblk + 4 * eg;

    unsigned long long a00 = 0ull, a01 = 0ull, a10 = 0ull, a11 = 0ull;
    const float* hp = hs + s0;

    for (int ph = 0; ph < 2; ph++) {
        int kb = ph * KP;
        // fill hs slab for this phase
        for (int s = warp; s < TS; s += 16) {
            int cls = scls[s];
            float xx0 = sx0[s], xx1 = sx1[s];
            const float* urow = g_u + cls * FC1N + kb;
            const float2* wxp = g_wx + kb;
            for (int k = lane; k < KP; k += 32) {
                float2 wv = wxp[k];
                float v = fmaf(xx0, wv.x, fmaf(xx1, wv.y, urow[k]));
                hs[k * HR + s] = fmaxf(v, 0.f);
            }
        }
        __syncthreads();

        const float* wp = ws + kb * WR + e0;
        // software pipeline: prefetch distance 2 k
        float2 h0 = *(const float2*)(hp);
        float2 h1 = *(const float2*)(hp + HR);
        float4 w0 = *(const float4*)(wp);
        float4 w1 = *(const float4*)(wp + WR);
#pragma unroll 2
        for (int k = 0; k < KP; k += 2) {
            float2 hn0 = *(const float2*)(hp + (k + 2) * HR);
            float4 wn0 = *(const float4*)(wp + (k + 2) * WR);
            float2 hn1 = *(const float2*)(hp + (k + 3) * HR);
            float4 wn1 = *(const float4*)(wp + (k + 3) * WR);
            FMA8(h0, w0);
            FMA8(h1, w1);
            h0 = hn0; w0 = wn0; h1 = hn1; w1 = wn1;
        }
        __syncthreads();  // hs refill of next phase must wait for reads
    }

    // unpack logits (+bias) into Ls[s][e]
    {
        float v0, v1, v2, v3, u0, u1, u2, u3;
        asm("mov.b64 {%0,%1}, %2;" : "=f"(v0), "=f"(v1) : "l"(a00));
        asm("mov.b64 {%0,%1}, %2;" : "=f"(v2), "=f"(v3) : "l"(a01));
        asm("mov.b64 {%0,%1}, %2;" : "=f"(u0), "=f"(u1) : "l"(a10));
        asm("mov.b64 {%0,%1}, %2;" : "=f"(u2), "=f"(u3) : "l"(a11));
        float* L0 = Ls + s0 * LR + e0;
        float* L1 = Ls + (s0 + 1) * LR + e0;
        float b0 = b2s[e0], b1 = b2s[e0 + 1], b2 = b2s[e0 + 2], b3 = b2s[e0 + 3];
        L0[0] = v0 + b0; L0[1] = v1 + b1; L0[2] = v2 + b2; L0[3] = v3 + b3;
        L1[0] = u0 + b0; L1[1] = u1 + b1; L1[2] = u2 + b2; L1[3] = u3 + b3;
    }
    __syncthreads();

    // softmax over 64 + expert mix; warp-per-sample (2 experts per lane)
    for (int s = warp; s < TS; s += 16) {
        float l0 = Ls[s * LR + lane];
        float l1 = Ls[s * LR + 32 + lane];
        float m = fmaxf(l0, l1);
#pragma unroll
        for (int off = 16; off; off >>= 1) m = fmaxf(m, __shfl_xor_sync(~0u, m, off));
        float ee0 = __expf(l0 - m), ee1 = __expf(l1 - m);
        float d0 = sd0[s], d1 = sd1[s];
        const float* G0 = Gs + lane * 4;
        const float* G1 = Gs + (lane + 32) * 4;
        float y0 = ee0 * (G0[0] * d0 + G0[1] * d1) + ee1 * (G1[0] * d0 + G1[1] * d1);
        float y1 = ee0 * (G0[2] * d0 + G0[3] * d1) + ee1 * (G1[2] * d0 + G1[3] * d1);
        float Z = ee0 + ee1;
#pragma unroll
        for (int off = 16; off; off >>= 1) {
            y0 += __shfl_xor_sync(~0u, y0, off);
            y1 += __shfl_xor_sync(~0u, y1, off);
            Z += __shfl_xor_sync(~0u, Z, off);
        }
        if (lane == 0) {
            float inv = 1.f / Z;
            out[2 * (base + s) + 0] = y0 * inv;
            out[2 * (base + s) + 1] = y1 * inv;
        }
    }
}

// ---------------------------------------------------------------------------
extern "C" void kernel_launch(void* const* d_in, const int* in_sizes, int n_in,
                              void* d_out, int out_size) {
    const float* x       = (const float*)d_in[0];
    const int*   cls     = (const int*)d_in[1];
    const float* images  = (const float*)d_in[2];
    const float* conv1_w = (const float*)d_in[3];
    const float* conv1_b = (const float*)d_in[4];
    const float* conv2_w = (const float*)d_in[5];
    const float* conv2_b = (const float*)d_in[6];
    const float* fc1_w   = (const float*)d_in[7];
    const float* fc1_b   = (const float*)d_in[8];
    const float* fc2_w   = (const float*)d_in[9];
    const float* fc2_b   = (const float*)d_in[10];
    const float* A_B     = (const float*)d_in[11];
    const float* A_C     = (const float*)d_in[12];
    const float* x_tar   = (const float*)d_in[13];
    float* out = (float*)d_out;

    cudaFuncSetAttribute(fc1_kernel, cudaFuncAttributeMaxDynamicSharedMemorySize,
                         FC1SMEM);
    cudaFuncSetAttribute(moe_kernel, cudaFuncAttributeMaxDynamicSharedMemorySize,
                         SMEMC);

    conv1_kernel<<<N_CLASSES * 5, 512>>>(images, conv1_w, conv1_b, fc1_w, fc2_w);
    conv2_kernel<<<N_CLASSES * 10, 256>>>(conv2_w, conv2_b);
    fc1_kernel<<<128, 256, FC1SMEM>>>(fc1_w, fc1_b);
    moe_kernel<<<BATCH / TS, 512, SMEMC>>>(x, cls, fc2_b, A_B, A_C, x_tar, out);
    (void)in_sizes; (void)n_in; (void)out_size;
}